// round 5
// baseline (speedup 1.0000x reference)
#include <cuda_runtime.h>
#include <math.h>

#define Vv      40
#define Ee      512
#define Hh      512
#define DKk     512
#define DVv     512
#define TENC    8192
#define MAXLEN  200
#define EOSI    38
#define SCALE   0.04419417382415922f   /* 1/sqrt(512) */

#define NB      128          /* 64 keys, 4 h-rows per block */
#define TPB     1024
#define ROWS_PB 4
#define KEYS_PB 64

// -------- persistent device scratch --------
__device__ float  g_GIT[Vv*3*Hh];       // [best][1536]
__device__ float  g_WV[TENC*Vv];        // values @ w_out[:, :512]^T
__device__ float4 g_hT4[Hh/2];          // {h2i, tag, h2i+1, tag}
__device__ float2 g_pUT[(Vv+1)*NB];     // rows 0..39: pU, row 40: denom; {val, tag}
__device__ float2 g_pOHT[Vv];           // {w_out[:,512:]@h row, tag}

// -------- weak L2-direct vector ops --------
__device__ __forceinline__ float2 ldcg2(const float2* p) {
    float2 v;
    asm volatile("ld.global.cg.v2.f32 {%0,%1},[%2];"
                 : "=f"(v.x), "=f"(v.y) : "l"(p) : "memory");
    return v;
}
__device__ __forceinline__ float4 ldcg4(const float4* p) {
    float4 v;
    asm volatile("ld.global.cg.v4.f32 {%0,%1,%2,%3},[%4];"
                 : "=f"(v.x), "=f"(v.y), "=f"(v.z), "=f"(v.w) : "l"(p) : "memory");
    return v;
}
__device__ __forceinline__ void stcg2(float2* p, float2 v) {
    asm volatile("st.global.cg.v2.f32 [%0],{%1,%2};"
                 :: "l"(p), "f"(v.x), "f"(v.y) : "memory");
}
__device__ __forceinline__ void stcg4(float4* p, float4 v) {
    asm volatile("st.global.cg.v4.f32 [%0],{%1,%2,%3,%4};"
                 :: "l"(p), "f"(v.x), "f"(v.y), "f"(v.z), "f"(v.w) : "memory");
}

// -------- reset tags every launch (graph-replay safe) --------
__global__ void reset_kernel()
{
    int tid = threadIdx.x;
    for (int i = tid; i < (Vv+1)*NB; i += blockDim.x) g_pUT[i] = make_float2(0.f, 0.f);
    for (int i = tid; i < Hh/2;      i += blockDim.x) g_hT4[i] = make_float4(0.f,0.f,0.f,0.f);
    if (tid < Vv) g_pOHT[tid] = make_float2(0.f, 0.f);
}

// -------- GIT[v][gid] = dot(w_ih[gid], embed[v]) + b_ih[gid] ----------------
__global__ void gi_kernel(const float* __restrict__ w_ih,
                          const float* __restrict__ b_ih,
                          const float* __restrict__ embed)
{
    extern __shared__ float sE[];              // embed [40][512] = 80 KB
    for (int i = threadIdx.x; i < Vv*Ee; i += blockDim.x) sE[i] = embed[i];
    __syncthreads();

    int lane = threadIdx.x & 31;
    int gid  = blockIdx.x * (blockDim.x >> 5) + (threadIdx.x >> 5);
    if (gid >= 3*Hh) return;

    float4 wreg[4];
    const float4* wr = (const float4*)(w_ih + (size_t)gid * Ee);
    #pragma unroll
    for (int j = 0; j < 4; ++j) wreg[j] = wr[lane + 32*j];
    float bb = b_ih[gid];

    for (int v = 0; v < Vv; ++v) {
        const float4* ev = (const float4*)(sE + v*Ee);
        float a = 0.f;
        #pragma unroll
        for (int j = 0; j < 4; ++j) {
            float4 e = ev[lane + 32*j];
            a = fmaf(wreg[j].x, e.x, a); a = fmaf(wreg[j].y, e.y, a);
            a = fmaf(wreg[j].z, e.z, a); a = fmaf(wreg[j].w, e.w, a);
        }
        #pragma unroll
        for (int o = 16; o > 0; o >>= 1) a += __shfl_down_sync(0xffffffffu, a, o);
        if (lane == 0) g_GIT[(size_t)v*(3*Hh) + gid] = a + bb;
    }
}

// -------- WV[t][k] = dot(values[t], w_out[k][0:512]) ------------------------
__global__ void wv_kernel(const float* __restrict__ enc,
                          const float* __restrict__ w_out)
{
    extern __shared__ float sW[];              // w_out[:, :512] = 80 KB
    for (int i = threadIdx.x; i < Vv*DVv; i += blockDim.x) {
        int k = i / DVv, j = i % DVv;
        sW[i] = w_out[(size_t)k*(DVv+Hh) + j];
    }
    __syncthreads();

    int lane  = threadIdx.x & 31;
    int gw    = blockIdx.x * (blockDim.x >> 5) + (threadIdx.x >> 5);
    int wspan = gridDim.x  * (blockDim.x >> 5);

    for (int t = gw; t < TENC; t += wspan) {
        float4 vreg[4];
        const float4* vr = (const float4*)(enc + (size_t)t*(DKk+DVv) + DKk);
        #pragma unroll
        for (int j = 0; j < 4; ++j) vreg[j] = vr[lane + 32*j];
        for (int k = 0; k < Vv; ++k) {
            const float4* wk = (const float4*)(sW + k*DVv);
            float a = 0.f;
            #pragma unroll
            for (int j = 0; j < 4; ++j) {
                float4 w = wk[lane + 32*j];
                a = fmaf(vreg[j].x, w.x, a); a = fmaf(vreg[j].y, w.y, a);
                a = fmaf(vreg[j].z, w.z, a); a = fmaf(vreg[j].w, w.w, a);
            }
            #pragma unroll
            for (int o = 16; o > 0; o >>= 1) a += __shfl_down_sync(0xffffffffu, a, o);
            if (lane == 0) g_WV[(size_t)t*Vv + k] = a;
        }
    }
}

// -------- persistent decoder ------------------------------------------------
__global__ void __launch_bounds__(TPB, 1)
dec_main(const float* __restrict__ enc,
         const float* __restrict__ hidden,
         const float* __restrict__ w_hh,
         const float* __restrict__ b_hh,
         const float* __restrict__ w_out,
         const float* __restrict__ b_out,
         float*       __restrict__ dout)
{
    __shared__ float h_sh[Hh];
    __shared__ float sGH[ROWS_PB][3];
    __shared__ float sU[32][41];
    __shared__ float sDen[32];
    __shared__ float sR[Vv+1][13];
    __shared__ float sOH[Vv];
    __shared__ float s_invden;

    const int tid  = threadIdx.x;
    const int wid  = tid >> 5;
    const int lane = tid & 31;
    const int b    = blockIdx.x;

    float* attn = dout + (MAXLEN*Vv + 1);
    const int t0   = b * KEYS_PB;
    const int row0 = b * ROWS_PB;
    int   mylen = MAXLEN;                      // warp0 lane0 of block 0
    float e0 = 0.f, e1 = 0.f;                  // this warp's 2 unnormalized weights

    // redundant-reduce thread mapping (tid < 492)
    const int rk = tid / 12, rj = tid % 12;

    // ---- preload h(-1) = hidden; precompute gh = w_hh @ hidden ----
    if (tid < Hh/4) ((float4*)h_sh)[tid] = ((const float4*)hidden)[tid];
    __syncthreads();

    #define COMPUTE_GH()                                                          \
    do {                                                                           \
        if (wid < 12) {                                                            \
            int rl = wid / 3, gate = wid % 3;                                      \
            const float4* wr = (const float4*)(w_hh +                              \
                               (size_t)(gate*Hh + row0 + rl) * Hh);                \
            const float4* hv4g = (const float4*)h_sh;                              \
            float a = 0.f;                                                         \
            _Pragma("unroll")                                                      \
            for (int j = 0; j < 4; ++j) {                                          \
                float4 w = wr[lane + 32*j], h = hv4g[lane + 32*j];                 \
                a = fmaf(w.x, h.x, a); a = fmaf(w.y, h.y, a);                      \
                a = fmaf(w.z, h.z, a); a = fmaf(w.w, h.w, a);                      \
            }                                                                      \
            _Pragma("unroll")                                                      \
            for (int o = 16; o > 0; o >>= 1) a += __shfl_xor_sync(0xffffffffu, a, o); \
            if (lane == 0) sGH[rl][gate] = a;                                      \
        }                                                                          \
    } while (0)

    // combine for this block's 4 rows on warp0 lanes 0-3; publish tagged h
    #define COMBINE_PUBLISH(BEST, TAGF)                                            \
    do {                                                                           \
        float hnv = 0.f;                                                           \
        if (lane < ROWS_PB) {                                                      \
            int row = row0 + lane;                                                 \
            const float* git = g_GIT + (size_t)(BEST) * (3*Hh);                    \
            float ghr = sGH[lane][0] + b_hh[row];                                  \
            float ghz = sGH[lane][1] + b_hh[Hh + row];                             \
            float ghn = sGH[lane][2] + b_hh[2*Hh + row];                           \
            float gir = git[row], giz = git[Hh + row], gin = git[2*Hh + row];      \
            float rr = 1.f/(1.f + __expf(-(gir + ghr)));                           \
            float zz = 1.f/(1.f + __expf(-(giz + ghz)));                           \
            float x  = gin + rr*ghn;                                               \
            float ex = __expf(2.f*x);                                              \
            float nn = (ex - 1.f)/(ex + 1.f);                                      \
            hnv = (1.f - zz)*nn + zz*h_sh[row];                                    \
        }                                                                          \
        float up = __shfl_down_sync(0xffffffffu, hnv, 1);                          \
        if (lane == 0) stcg4(&g_hT4[2*b    ], make_float4(hnv,(TAGF),up,(TAGF)));  \
        if (lane == 2) stcg4(&g_hT4[2*b + 1], make_float4(hnv,(TAGF),up,(TAGF)));  \
    } while (0)

    COMPUTE_GH();
    __syncthreads();

    for (int s = 0; s < MAXLEN; ++s) {
        const float tagf = (float)(s + 1);

        if (s > 0) {
            const float ptag = (float)s;
            // ---- poll all blocks' tagged partials (redundant, all blocks) ----
            float acc = 0.f, pohv = 0.f;
            for (;;) {
                int ok = 1;
                if (tid < 492) {
                    acc = 0.f;
                    for (int p = rj; p < NB; p += 12) {
                        float2 e = ldcg2(&g_pUT[rk*NB + p]);
                        ok &= (e.y >= ptag);
                        acc += e.x;
                    }
                } else if (tid >= 512 && tid < 512 + Vv) {
                    float2 e = ldcg2(&g_pOHT[tid - 512]);
                    ok = (e.y >= ptag);
                    pohv = e.x;
                }
                if (__syncthreads_and(ok)) break;
            }
            if (tid < 492) sR[rk][rj] = acc;
            else if (tid >= 512 && tid < 512 + Vv) sOH[tid - 512] = pohv;
            __syncthreads();

            // ---- warp0: invden, logits(s-1), argmax, combine, publish h(s) ----
            if (wid == 0) {
                float d = 0.f;
                #pragma unroll
                for (int q = 0; q < 12; ++q) d += sR[Vv][q];
                float inv = 1.0f / d;
                if (lane == 0) s_invden = inv;

                float v1, v2 = -3.4e38f;
                int   k1 = lane, k2 = lane + 32;
                {
                    float a = 0.f;
                    #pragma unroll
                    for (int q = 0; q < 12; ++q) a += sR[k1][q];
                    v1 = a*inv + sOH[k1] + b_out[k1];
                    if (b == 0) dout[(s-1)*Vv + k1] = v1;
                }
                if (lane < Vv - 32) {
                    float a = 0.f;
                    #pragma unroll
                    for (int q = 0; q < 12; ++q) a += sR[k2][q];
                    v2 = a*inv + sOH[k2] + b_out[k2];
                    if (b == 0) dout[(s-1)*Vv + k2] = v2;
                }
                float bv; int bi;
                if (v2 > v1) { bv = v2; bi = k2; } else { bv = v1; bi = k1; }
                #pragma unroll
                for (int o = 16; o > 0; o >>= 1) {
                    float ov = __shfl_xor_sync(0xffffffffu, bv, o);
                    int   oi = __shfl_xor_sync(0xffffffffu, bi, o);
                    if (ov > bv || (ov == bv && oi < bi)) { bv = ov; bi = oi; }
                }
                if (b == 0 && lane == 0 && bi == EOSI && mylen == MAXLEN) mylen = s - 1;
                COMBINE_PUBLISH(bi, tagf);
            }
            __syncthreads();

            // ---- store normalized attention row (s-1) from registers ----
            if (lane == 0) {
                float inv = s_invden;
                attn[(size_t)(s-1)*TENC + t0 + wid     ] = e0 * inv;
                attn[(size_t)(s-1)*TENC + t0 + wid + 32] = e1 * inv;
            }
        } else {
            // s == 0: input token is EOS, no reduce needed
            if (wid == 0) COMBINE_PUBLISH(EOSI, tagf);
        }

        // ---- poll tagged h chunks ----
        {
            float4 hv;
            for (;;) {
                int ok = 1;
                if (tid < Hh/2) {
                    hv = ldcg4(&g_hT4[tid]);
                    ok = (hv.y >= tagf) && (hv.w >= tagf);
                }
                if (__syncthreads_and(ok)) break;
            }
            if (tid < Hh/2) { h_sh[2*tid] = hv.x; h_sh[2*tid + 1] = hv.z; }
            __syncthreads();
        }

        // ---- pOutH row (blocks 1..40, warp 31, before its keys) ----
        if (b >= 1 && b <= Vv && wid == 31) {
            int k = b - 1;
            const float4* wr  = (const float4*)(w_out + (size_t)k*(DVv+Hh) + DVv);
            const float4* hv4 = (const float4*)h_sh;
            float acc = 0.f;
            #pragma unroll
            for (int j = 0; j < 4; ++j) {
                float4 w = wr[lane + 32*j], h = hv4[lane + 32*j];
                acc = fmaf(w.x, h.x, acc); acc = fmaf(w.y, h.y, acc);
                acc = fmaf(w.z, h.z, acc); acc = fmaf(w.w, h.w, acc);
            }
            #pragma unroll
            for (int o = 16; o > 0; o >>= 1) acc += __shfl_xor_sync(0xffffffffu, acc, o);
            if (lane == 0) stcg2(&g_pOHT[k], make_float2(acc, tagf));
        }

        // ---- attention over this block's 64 keys (L1-resident) ----
        {
            const float4* hv4 = (const float4*)h_sh;
            float4 h0 = hv4[lane], h1 = hv4[lane+32], h2 = hv4[lane+64], h3 = hv4[lane+96];
            float acc0 = 0.f, acc1 = 0.f, den = 0.f;
            #pragma unroll
            for (int it = 0; it < 2; ++it) {
                int t = t0 + wid + it*32;
                const float4* kr = (const float4*)(enc + (size_t)t*(DKk+DVv));
                float4 k0 = kr[lane], k1 = kr[lane+32], k2 = kr[lane+64], k3 = kr[lane+96];
                float a = 0.f;
                a = fmaf(k0.x, h0.x, a); a = fmaf(k0.y, h0.y, a);
                a = fmaf(k0.z, h0.z, a); a = fmaf(k0.w, h0.w, a);
                a = fmaf(k1.x, h1.x, a); a = fmaf(k1.y, h1.y, a);
                a = fmaf(k1.z, h1.z, a); a = fmaf(k1.w, h1.w, a);
                a = fmaf(k2.x, h2.x, a); a = fmaf(k2.y, h2.y, a);
                a = fmaf(k2.z, h2.z, a); a = fmaf(k2.w, h2.w, a);
                a = fmaf(k3.x, h3.x, a); a = fmaf(k3.y, h3.y, a);
                a = fmaf(k3.z, h3.z, a); a = fmaf(k3.w, h3.w, a);
                #pragma unroll
                for (int o = 16; o > 0; o >>= 1) a += __shfl_xor_sync(0xffffffffu, a, o);
                float e = __expf(a * SCALE);
                if (it == 0) e0 = e; else e1 = e;
                den += e;
                acc0 = fmaf(e, g_WV[(size_t)t*Vv + lane], acc0);
                if (lane < Vv - 32)
                    acc1 = fmaf(e, g_WV[(size_t)t*Vv + 32 + lane], acc1);
            }
            sU[wid][lane] = acc0;
            if (lane < Vv - 32) sU[wid][32 + lane] = acc1;
            if (lane == 0) sDen[wid] = den;
        }
        __syncthreads();

        if (tid < Vv) {
            float a = 0.f;
            #pragma unroll
            for (int w = 0; w < 32; ++w) a += sU[w][tid];
            stcg2(&g_pUT[tid*NB + b], make_float2(a, tagf));
        } else if (tid == Vv) {
            float d = 0.f;
            #pragma unroll
            for (int w = 0; w < 32; ++w) d += sDen[w];
            stcg2(&g_pUT[Vv*NB + b], make_float2(d, tagf));
        }

        // gh = w_hh @ h(s), for the next combine (off detect path)
        if (s < MAXLEN-1) COMPUTE_GH();
    }

    // ---- tail: reduce step 199, final logits/argmax, lens, last attn row ----
    {
        const float ptag = (float)MAXLEN;
        float acc = 0.f, pohv = 0.f;
        for (;;) {
            int ok = 1;
            if (tid < 492) {
                acc = 0.f;
                for (int p = rj; p < NB; p += 12) {
                    float2 e = ldcg2(&g_pUT[rk*NB + p]);
                    ok &= (e.y >= ptag);
                    acc += e.x;
                }
            } else if (tid >= 512 && tid < 512 + Vv) {
                float2 e = ldcg2(&g_pOHT[tid - 512]);
                ok = (e.y >= ptag);
                pohv = e.x;
            }
            if (__syncthreads_and(ok)) break;
        }
        if (tid < 492) sR[rk][rj] = acc;
        else if (tid >= 512 && tid < 512 + Vv) sOH[tid - 512] = pohv;
        __syncthreads();

        if (wid == 0) {
            float d = 0.f;
            #pragma unroll
            for (int q = 0; q < 12; ++q) d += sR[Vv][q];
            float inv = 1.0f / d;
            if (lane == 0) s_invden = inv;

            float v1, v2 = -3.4e38f;
            int   k1 = lane, k2 = lane + 32;
            {
                float a = 0.f;
                #pragma unroll
                for (int q = 0; q < 12; ++q) a += sR[k1][q];
                v1 = a*inv + sOH[k1] + b_out[k1];
                if (b == 0) dout[(MAXLEN-1)*Vv + k1] = v1;
            }
            if (lane < Vv - 32) {
                float a = 0.f;
                #pragma unroll
                for (int q = 0; q < 12; ++q) a += sR[k2][q];
                v2 = a*inv + sOH[k2] + b_out[k2];
                if (b == 0) dout[(MAXLEN-1)*Vv + k2] = v2;
            }
            if (b == 0) {
                float bv; int bi;
                if (v2 > v1) { bv = v2; bi = k2; } else { bv = v1; bi = k1; }
                #pragma unroll
                for (int o = 16; o > 0; o >>= 1) {
                    float ov = __shfl_xor_sync(0xffffffffu, bv, o);
                    int   oi = __shfl_xor_sync(0xffffffffu, bi, o);
                    if (ov > bv || (ov == bv && oi < bi)) { bv = ov; bi = oi; }
                }
                if (lane == 0) {
                    if (bi == EOSI && mylen == MAXLEN) mylen = MAXLEN - 1;
                    dout[MAXLEN*Vv] = (float)mylen;
                }
            }
        }
        __syncthreads();
        if (lane == 0) {
            float inv = s_invden;
            attn[(size_t)(MAXLEN-1)*TENC + t0 + wid     ] = e0 * inv;
            attn[(size_t)(MAXLEN-1)*TENC + t0 + wid + 32] = e1 * inv;
        }
    }
}

// ---------------------------------------------------------------------------
extern "C" void kernel_launch(void* const* d_in, const int* in_sizes, int n_in,
                              void* d_out, int out_size)
{
    const float* enc    = (const float*)d_in[0];
    const float* hidden = (const float*)d_in[1];
    const float* embed  = (const float*)d_in[2];
    const float* w_ih   = (const float*)d_in[3];
    const float* w_hh   = (const float*)d_in[4];
    const float* b_ih   = (const float*)d_in[5];
    const float* b_hh   = (const float*)d_in[6];
    const float* w_out  = (const float*)d_in[7];
    const float* b_out  = (const float*)d_in[8];
    float*       out    = (float*)d_out;

    cudaFuncSetAttribute(gi_kernel, cudaFuncAttributeMaxDynamicSharedMemorySize, 81920);
    cudaFuncSetAttribute(wv_kernel, cudaFuncAttributeMaxDynamicSharedMemorySize, 81920);

    reset_kernel<<<1, 1024>>>();
    gi_kernel<<<192, 256, 81920>>>(w_ih, b_ih, embed);
    wv_kernel<<<256, 256, 81920>>>(enc, w_out);
    dec_main<<<NB, TPB>>>(enc, hidden, w_hh, b_hh, w_out, b_out, out);
}

// round 8
// speedup vs baseline: 1.9128x; 1.9128x over previous
#include <cuda_runtime.h>
#include <math.h>

#define Vv      40
#define Ee      512
#define Hh      512
#define DKk     512
#define DVv     512
#define TENC    8192
#define MAXLEN  200
#define EOSI    38
#define SCALE   0.04419417382415922f   /* 1/sqrt(512) */

#define NB      128          /* 64 keys, 4 h-rows per block */
#define TPB     1024
#define ROWS_PB 4
#define KEYS_PB 64
#define NCPY    8            /* broadcast replication */

// -------- persistent device scratch --------
__device__ float  g_GIT[Vv*3*Hh];                    // [best][1536]
__device__ float  g_WV[TENC*Vv];                     // values @ w_out[:, :512]^T
__device__ __align__(16) float4 g_hT4R[NCPY][Hh/2];  // 8 copies {h2i,tag,h2i+1,tag}
__device__ __align__(16) float2 g_pUT[(Vv+1)*NB];    // rows 0..39 pU, row 40 denom {val,tag}
__device__ __align__(16) float2 g_pOHT[Vv];          // {w_out[:,512:]@h row, tag}
__device__ __align__(16) float4 g_verdR[NCPY*8];     // 8 copies 128B apart {best,inv,tag,0}

// -------- weak L2-direct vector ops --------
__device__ __forceinline__ float2 ldcg2(const float2* p) {
    float2 v;
    asm volatile("ld.global.cg.v2.f32 {%0,%1},[%2];"
                 : "=f"(v.x), "=f"(v.y) : "l"(p) : "memory");
    return v;
}
__device__ __forceinline__ float4 ldcg4(const float4* p) {
    float4 v;
    asm volatile("ld.global.cg.v4.f32 {%0,%1,%2,%3},[%4];"
                 : "=f"(v.x), "=f"(v.y), "=f"(v.z), "=f"(v.w) : "l"(p) : "memory");
    return v;
}
__device__ __forceinline__ void stcg2(float2* p, float2 v) {
    asm volatile("st.global.cg.v2.f32 [%0],{%1,%2};"
                 :: "l"(p), "f"(v.x), "f"(v.y) : "memory");
}
__device__ __forceinline__ void stcg4(float4* p, float4 v) {
    asm volatile("st.global.cg.v4.f32 [%0],{%1,%2,%3,%4};"
                 :: "l"(p), "f"(v.x), "f"(v.y), "f"(v.z), "f"(v.w) : "memory");
}

// -------- reset tags every launch (graph-replay safe) --------
__global__ void reset_kernel()
{
    int tid = threadIdx.x;
    for (int i = tid; i < (Vv+1)*NB; i += blockDim.x) g_pUT[i] = make_float2(0.f, 0.f);
    for (int i = tid; i < NCPY*Hh/2; i += blockDim.x)
        ((float4*)g_hT4R)[i] = make_float4(0.f,0.f,0.f,0.f);
    if (tid < Vv) g_pOHT[tid] = make_float2(0.f, 0.f);
    if (tid < NCPY*8) g_verdR[tid] = make_float4(0.f,0.f,0.f,0.f);
}

// -------- GIT[v][gid] = dot(w_ih[gid], embed[v]) + b_ih[gid] ----------------
__global__ void gi_kernel(const float* __restrict__ w_ih,
                          const float* __restrict__ b_ih,
                          const float* __restrict__ embed)
{
    extern __shared__ float sE[];
    for (int i = threadIdx.x; i < Vv*Ee; i += blockDim.x) sE[i] = embed[i];
    __syncthreads();

    int lane = threadIdx.x & 31;
    int gid  = blockIdx.x * (blockDim.x >> 5) + (threadIdx.x >> 5);
    if (gid >= 3*Hh) return;

    float4 wreg[4];
    const float4* wr = (const float4*)(w_ih + (size_t)gid * Ee);
    #pragma unroll
    for (int j = 0; j < 4; ++j) wreg[j] = wr[lane + 32*j];
    float bb = b_ih[gid];

    for (int v = 0; v < Vv; ++v) {
        const float4* ev = (const float4*)(sE + v*Ee);
        float a = 0.f;
        #pragma unroll
        for (int j = 0; j < 4; ++j) {
            float4 e = ev[lane + 32*j];
            a = fmaf(wreg[j].x, e.x, a); a = fmaf(wreg[j].y, e.y, a);
            a = fmaf(wreg[j].z, e.z, a); a = fmaf(wreg[j].w, e.w, a);
        }
        #pragma unroll
        for (int o = 16; o > 0; o >>= 1) a += __shfl_down_sync(0xffffffffu, a, o);
        if (lane == 0) g_GIT[(size_t)v*(3*Hh) + gid] = a + bb;
    }
}

// -------- WV[t][k] = dot(values[t], w_out[k][0:512]) ------------------------
__global__ void wv_kernel(const float* __restrict__ enc,
                          const float* __restrict__ w_out)
{
    extern __shared__ float sW[];
    for (int i = threadIdx.x; i < Vv*DVv; i += blockDim.x) {
        int k = i / DVv, j = i % DVv;
        sW[i] = w_out[(size_t)k*(DVv+Hh) + j];
    }
    __syncthreads();

    int lane  = threadIdx.x & 31;
    int gw    = blockIdx.x * (blockDim.x >> 5) + (threadIdx.x >> 5);
    int wspan = gridDim.x  * (blockDim.x >> 5);

    for (int t = gw; t < TENC; t += wspan) {
        float4 vreg[4];
        const float4* vr = (const float4*)(enc + (size_t)t*(DKk+DVv) + DKk);
        #pragma unroll
        for (int j = 0; j < 4; ++j) vreg[j] = vr[lane + 32*j];
        for (int k = 0; k < Vv; ++k) {
            const float4* wk = (const float4*)(sW + k*DVv);
            float a = 0.f;
            #pragma unroll
            for (int j = 0; j < 4; ++j) {
                float4 w = wk[lane + 32*j];
                a = fmaf(vreg[j].x, w.x, a); a = fmaf(vreg[j].y, w.y, a);
                a = fmaf(vreg[j].z, w.z, a); a = fmaf(vreg[j].w, w.w, a);
            }
            #pragma unroll
            for (int o = 16; o > 0; o >>= 1) a += __shfl_down_sync(0xffffffffu, a, o);
            if (lane == 0) g_WV[(size_t)t*Vv + k] = a;
        }
    }
}

// -------- persistent decoder ------------------------------------------------
__global__ void __launch_bounds__(TPB, 1)
dec_main(const float* __restrict__ enc,
         const float* __restrict__ hidden,
         const float* __restrict__ w_hh,
         const float* __restrict__ b_hh,
         const float* __restrict__ w_out,
         const float* __restrict__ b_out,
         float*       __restrict__ dout)
{
    __shared__ float  h_sh[Hh];
    __shared__ float  sGH[ROWS_PB][3];
    __shared__ float  sU[32][41];
    __shared__ float  sDen[32];
    __shared__ float  sRR[Vv+1][16];
    __shared__ float  sOH[Vv];
    __shared__ float4 s_vd;

    const int tid  = threadIdx.x;
    const int wid  = tid >> 5;
    const int lane = tid & 31;
    const int b    = blockIdx.x;

    float* attn = dout + (MAXLEN*Vv + 1);
    const int t0   = b * KEYS_PB;
    const int row0 = b * ROWS_PB;
    int   mylen = MAXLEN;                      // block0 warp0 lane0
    float e0 = 0.f, e1 = 0.f;

    // ---- preload h(-1) = hidden; precompute gh = w_hh @ hidden ----
    if (tid < Hh/4) ((float4*)h_sh)[tid] = ((const float4*)hidden)[tid];
    __syncthreads();

    #define COMPUTE_GH()                                                          \
    do {                                                                           \
        if (wid < 12) {                                                            \
            int rl = wid / 3, gate = wid % 3;                                      \
            const float4* wr = (const float4*)(w_hh +                              \
                               (size_t)(gate*Hh + row0 + rl) * Hh);                \
            const float4* hv4g = (const float4*)h_sh;                              \
            float a = 0.f;                                                         \
            _Pragma("unroll")                                                      \
            for (int j = 0; j < 4; ++j) {                                          \
                float4 w = wr[lane + 32*j], h = hv4g[lane + 32*j];                 \
                a = fmaf(w.x, h.x, a); a = fmaf(w.y, h.y, a);                      \
                a = fmaf(w.z, h.z, a); a = fmaf(w.w, h.w, a);                      \
            }                                                                      \
            _Pragma("unroll")                                                      \
            for (int o = 16; o > 0; o >>= 1) a += __shfl_xor_sync(0xffffffffu, a, o); \
            if (lane == 0) sGH[rl][gate] = a;                                      \
        }                                                                          \
    } while (0)

    // combine on warp0 lanes 0-3; publish tagged h to all NCPY copies
    #define COMBINE_PUBLISH(BEST, TAGF)                                            \
    do {                                                                           \
        float hnv = 0.f;                                                           \
        if (lane < ROWS_PB) {                                                      \
            int row = row0 + lane;                                                 \
            const float* git = g_GIT + (size_t)(BEST) * (3*Hh);                    \
            float ghr = sGH[lane][0] + b_hh[row];                                  \
            float ghz = sGH[lane][1] + b_hh[Hh + row];                             \
            float ghn = sGH[lane][2] + b_hh[2*Hh + row];                           \
            float gir = git[row], giz = git[Hh + row], gin = git[2*Hh + row];      \
            float rr = 1.f/(1.f + __expf(-(gir + ghr)));                           \
            float zz = 1.f/(1.f + __expf(-(giz + ghz)));                           \
            float x  = gin + rr*ghn;                                               \
            float ex = __expf(2.f*x);                                              \
            float nn = (ex - 1.f)/(ex + 1.f);                                      \
            hnv = (1.f - zz)*nn + zz*h_sh[row];                                    \
        }                                                                          \
        float up = __shfl_down_sync(0xffffffffu, hnv, 1);                          \
        if (lane == 0) {                                                           \
            float4 pk = make_float4(hnv,(TAGF),up,(TAGF));                         \
            _Pragma("unroll")                                                      \
            for (int c = 0; c < NCPY; ++c) stcg4(&g_hT4R[c][2*b], pk);             \
        }                                                                          \
        if (lane == 2) {                                                           \
            float4 pk = make_float4(hnv,(TAGF),up,(TAGF));                         \
            _Pragma("unroll")                                                      \
            for (int c = 0; c < NCPY; ++c) stcg4(&g_hT4R[c][2*b + 1], pk);         \
        }                                                                          \
    } while (0)

    COMPUTE_GH();
    __syncthreads();

    int best = EOSI;

    for (int s = 0; s < MAXLEN; ++s) {
        const float tagf = (float)(s + 1);

        // ---- consume verdict(s-1); store normalized attn row (s-1) ----
        if (s > 0) {
            const float ptag = (float)s;
            for (;;) {
                int ok = 1;
                if (tid == 0) {
                    float4 v = ldcg4(&g_verdR[(b & (NCPY-1))*8]);
                    s_vd = v; ok = (v.z >= ptag);
                }
                if (__syncthreads_and(ok)) break;
            }
            best = (int)s_vd.x;
            if (lane == 0) {
                float inv = s_vd.y;
                attn[(size_t)(s-1)*TENC + t0 + wid     ] = e0 * inv;
                attn[(size_t)(s-1)*TENC + t0 + wid + 32] = e1 * inv;
            }
        }

        // ---- combine & publish h(s) (warp 0) ----
        if (wid == 0) COMBINE_PUBLISH(best, tagf);

        // ---- h poll: loop-exit barrier orders combine's h_sh reads before writes ----
        {
            float4 hv;
            for (;;) {
                int ok = 1;
                if (tid < Hh/2) {
                    hv = ldcg4(&g_hT4R[b & (NCPY-1)][tid]);
                    ok = (hv.y >= tagf) && (hv.w >= tagf);
                }
                if (__syncthreads_and(ok)) break;
            }
            if (tid < Hh/2) { h_sh[2*tid] = hv.x; h_sh[2*tid + 1] = hv.z; }
            __syncthreads();
        }

        // ---- pOutH row (blocks 1..40, warp 31) ----
        if (b >= 1 && b <= Vv && wid == 31) {
            int k = b - 1;
            const float4* wr  = (const float4*)(w_out + (size_t)k*(DVv+Hh) + DVv);
            const float4* hv4 = (const float4*)h_sh;
            float acc = 0.f;
            #pragma unroll
            for (int j = 0; j < 4; ++j) {
                float4 w = wr[lane + 32*j], h = hv4[lane + 32*j];
                acc = fmaf(w.x, h.x, acc); acc = fmaf(w.y, h.y, acc);
                acc = fmaf(w.z, h.z, acc); acc = fmaf(w.w, h.w, acc);
            }
            #pragma unroll
            for (int o = 16; o > 0; o >>= 1) acc += __shfl_xor_sync(0xffffffffu, acc, o);
            if (lane == 0) stcg2(&g_pOHT[k], make_float2(acc, tagf));
        }

        // ---- attention over this block's 64 keys (L1-resident) ----
        {
            const float4* hv4 = (const float4*)h_sh;
            float4 h0 = hv4[lane], h1 = hv4[lane+32], h2 = hv4[lane+64], h3 = hv4[lane+96];
            float acc0 = 0.f, acc1 = 0.f, den = 0.f;
            #pragma unroll
            for (int it = 0; it < 2; ++it) {
                int t = t0 + wid + it*32;
                const float4* kr = (const float4*)(enc + (size_t)t*(DKk+DVv));
                float4 k0 = kr[lane], k1 = kr[lane+32], k2 = kr[lane+64], k3 = kr[lane+96];
                float a = 0.f;
                a = fmaf(k0.x, h0.x, a); a = fmaf(k0.y, h0.y, a);
                a = fmaf(k0.z, h0.z, a); a = fmaf(k0.w, h0.w, a);
                a = fmaf(k1.x, h1.x, a); a = fmaf(k1.y, h1.y, a);
                a = fmaf(k1.z, h1.z, a); a = fmaf(k1.w, h1.w, a);
                a = fmaf(k2.x, h2.x, a); a = fmaf(k2.y, h2.y, a);
                a = fmaf(k2.z, h2.z, a); a = fmaf(k2.w, h2.w, a);
                a = fmaf(k3.x, h3.x, a); a = fmaf(k3.y, h3.y, a);
                a = fmaf(k3.z, h3.z, a); a = fmaf(k3.w, h3.w, a);
                #pragma unroll
                for (int o = 16; o > 0; o >>= 1) a += __shfl_xor_sync(0xffffffffu, a, o);
                float e = __expf(a * SCALE);
                if (it == 0) e0 = e; else e1 = e;
                den += e;
                acc0 = fmaf(e, g_WV[(size_t)t*Vv + lane], acc0);
                if (lane < Vv - 32)
                    acc1 = fmaf(e, g_WV[(size_t)t*Vv + 32 + lane], acc1);
            }
            sU[wid][lane] = acc0;
            if (lane < Vv - 32) sU[wid][32 + lane] = acc1;
            if (lane == 0) sDen[wid] = den;
        }
        __syncthreads();

        // ---- publish tagged partials ----
        if (tid < Vv) {
            float a = 0.f;
            #pragma unroll
            for (int w = 0; w < 32; ++w) a += sU[w][tid];
            stcg2(&g_pUT[tid*NB + b], make_float2(a, tagf));
        } else if (tid == Vv) {
            float d = 0.f;
            #pragma unroll
            for (int w = 0; w < 32; ++w) d += sDen[w];
            stcg2(&g_pUT[Vv*NB + b], make_float2(d, tagf));
        }

        // gh = w_hh @ h(s) for the next combine (off detect path)
        if (s < MAXLEN-1) COMPUTE_GH();

        // ---- block 0: gather partials, logits(s), argmax, publish verdict ----
        if (b == 0) {
            const int r = tid >> 4, j = tid & 15;
            float acc = 0.f, pv = 0.f;
            for (;;) {
                int ok = 1;
                if (tid < 656) {
                    const float4* base = (const float4*)g_pUT + r*(NB/2);
                    acc = 0.f;
                    #pragma unroll
                    for (int q = 0; q < 4; ++q) {
                        float4 e = ldcg4(base + j + 16*q);
                        ok &= (e.y >= tagf) & (e.w >= tagf);
                        acc += e.x + e.z;
                    }
                } else if (tid >= 672 && tid < 672 + Vv) {
                    float2 e = ldcg2(&g_pOHT[tid - 672]);
                    ok = (e.y >= tagf);
                    pv = e.x;
                }
                if (__syncthreads_and(ok)) break;
            }
            if (tid < 656) sRR[r][j] = acc;
            else if (tid >= 672 && tid < 672 + Vv) sOH[tid - 672] = pv;
            __syncthreads();

            if (wid == 0) {
                float d = 0.f;
                #pragma unroll
                for (int q = 0; q < 16; ++q) d += sRR[Vv][q];
                float inv = 1.0f / d;

                float v1, v2 = -3.4e38f;
                int   k1 = lane, k2 = lane + 32;
                {
                    float a = 0.f;
                    #pragma unroll
                    for (int q = 0; q < 16; ++q) a += sRR[k1][q];
                    v1 = a*inv + sOH[k1] + b_out[k1];
                    dout[s*Vv + k1] = v1;
                }
                if (lane < Vv - 32) {
                    float a = 0.f;
                    #pragma unroll
                    for (int q = 0; q < 16; ++q) a += sRR[k2][q];
                    v2 = a*inv + sOH[k2] + b_out[k2];
                    dout[s*Vv + k2] = v2;
                }
                float bv; int bi;
                if (v2 > v1) { bv = v2; bi = k2; } else { bv = v1; bi = k1; }
                #pragma unroll
                for (int o = 16; o > 0; o >>= 1) {
                    float ov = __shfl_xor_sync(0xffffffffu, bv, o);
                    int   oi = __shfl_xor_sync(0xffffffffu, bi, o);
                    if (ov > bv || (ov == bv && oi < bi)) { bv = ov; bi = oi; }
                }
                if (lane == 0) {
                    if (bi == EOSI && mylen == MAXLEN) mylen = s;
                    if (s == MAXLEN-1) dout[MAXLEN*Vv] = (float)mylen;   // lens
                }
                if (lane < NCPY)
                    stcg4(&g_verdR[lane*8], make_float4((float)bi, inv, tagf, 0.f));
            }
        }
    }

    // ---- tail: consume verdict(199) for final attention row ----
    {
        const float ptag = (float)MAXLEN;
        for (;;) {
            int ok = 1;
            if (tid == 0) {
                float4 v = ldcg4(&g_verdR[(b & (NCPY-1))*8]);
                s_vd = v; ok = (v.z >= ptag);
            }
            if (__syncthreads_and(ok)) break;
        }
        if (lane == 0) {
            float inv = s_vd.y;
            attn[(size_t)(MAXLEN-1)*TENC + t0 + wid     ] = e0 * inv;
            attn[(size_t)(MAXLEN-1)*TENC + t0 + wid + 32] = e1 * inv;
        }
    }
}

// ---------------------------------------------------------------------------
extern "C" void kernel_launch(void* const* d_in, const int* in_sizes, int n_in,
                              void* d_out, int out_size)
{
    const float* enc    = (const float*)d_in[0];
    const float* hidden = (const float*)d_in[1];
    const float* embed  = (const float*)d_in[2];
    const float* w_ih   = (const float*)d_in[3];
    const float* w_hh   = (const float*)d_in[4];
    const float* b_ih   = (const float*)d_in[5];
    const float* b_hh   = (const float*)d_in[6];
    const float* w_out  = (const float*)d_in[7];
    const float* b_out  = (const float*)d_in[8];
    float*       out    = (float*)d_out;

    cudaFuncSetAttribute(gi_kernel, cudaFuncAttributeMaxDynamicSharedMemorySize, 81920);
    cudaFuncSetAttribute(wv_kernel, cudaFuncAttributeMaxDynamicSharedMemorySize, 81920);

    reset_kernel<<<1, 1024>>>();
    gi_kernel<<<192, 256, 81920>>>(w_ih, b_ih, embed);
    wv_kernel<<<256, 256, 81920>>>(enc, w_out);
    dec_main<<<NB, TPB>>>(enc, hidden, w_hh, b_hh, w_out, b_out, out);
}

// round 9
// speedup vs baseline: 2.1197x; 1.1082x over previous
#include <cuda_runtime.h>
#include <math.h>

#define Vv      40
#define Ee      512
#define Hh      512
#define DKk     512
#define DVv     512
#define TENC    8192
#define MAXLEN  200
#define EOSI    38
#define SCALE   0.04419417382415922f   /* 1/sqrt(512) */

#define NB      128          /* 64 keys, 4 h-rows per block */
#define TPB     1024
#define ROWS_PB 4
#define KEYS_PB 64
#define NCPY    8            /* broadcast replication */

// -------- persistent device scratch --------
__device__ float  g_GIT[Vv*3*Hh];                    // [best][1536]
__device__ float  g_WV[TENC*Vv];                     // values @ w_out[:, :512]^T
__device__ __align__(16) float4 g_hT4R[NCPY][Hh/2];  // 8 copies {h2i,tag,h2i+1,tag}
__device__ __align__(16) float2 g_pUT[(Vv+1)*NB];    // rows 0..39 pU, row 40 denom {val,tag}
__device__ __align__(16) float2 g_pOHT[Vv];          // {w_out[:,512:]@h row, tag}
__device__ __align__(16) float2 g_ghT[3*Hh];         // {w_hh@h row-gate, tag}, idx row*3+gate
__device__ __align__(16) float4 g_verdR[NCPY*8];     // 8 copies 128B apart {best,inv,tag,0}

// -------- weak L2-direct vector ops --------
__device__ __forceinline__ float2 ldcg2(const float2* p) {
    float2 v;
    asm volatile("ld.global.cg.v2.f32 {%0,%1},[%2];"
                 : "=f"(v.x), "=f"(v.y) : "l"(p) : "memory");
    return v;
}
__device__ __forceinline__ float4 ldcg4(const float4* p) {
    float4 v;
    asm volatile("ld.global.cg.v4.f32 {%0,%1,%2,%3},[%4];"
                 : "=f"(v.x), "=f"(v.y), "=f"(v.z), "=f"(v.w) : "l"(p) : "memory");
    return v;
}
__device__ __forceinline__ void stcg2(float2* p, float2 v) {
    asm volatile("st.global.cg.v2.f32 [%0],{%1,%2};"
                 :: "l"(p), "f"(v.x), "f"(v.y) : "memory");
}
__device__ __forceinline__ void stcg4(float4* p, float4 v) {
    asm volatile("st.global.cg.v4.f32 [%0],{%1,%2,%3,%4};"
                 :: "l"(p), "f"(v.x), "f"(v.y), "f"(v.z), "f"(v.w) : "memory");
}

// -------- reset tags every launch (graph-replay safe) --------
__global__ void reset_kernel()
{
    int tid = threadIdx.x;
    for (int i = tid; i < (Vv+1)*NB; i += blockDim.x) g_pUT[i] = make_float2(0.f, 0.f);
    for (int i = tid; i < NCPY*Hh/2; i += blockDim.x)
        ((float4*)g_hT4R)[i] = make_float4(0.f,0.f,0.f,0.f);
    for (int i = tid; i < 3*Hh; i += blockDim.x) g_ghT[i] = make_float2(0.f, 0.f);
    if (tid < Vv) g_pOHT[tid] = make_float2(0.f, 0.f);
    if (tid < NCPY*8) g_verdR[tid] = make_float4(0.f,0.f,0.f,0.f);
}

// -------- GIT[v][gid] = dot(w_ih[gid], embed[v]) + b_ih[gid] ----------------
__global__ void gi_kernel(const float* __restrict__ w_ih,
                          const float* __restrict__ b_ih,
                          const float* __restrict__ embed)
{
    extern __shared__ float sE[];
    for (int i = threadIdx.x; i < Vv*Ee; i += blockDim.x) sE[i] = embed[i];
    __syncthreads();

    int lane = threadIdx.x & 31;
    int gid  = blockIdx.x * (blockDim.x >> 5) + (threadIdx.x >> 5);
    if (gid >= 3*Hh) return;

    float4 wreg[4];
    const float4* wr = (const float4*)(w_ih + (size_t)gid * Ee);
    #pragma unroll
    for (int j = 0; j < 4; ++j) wreg[j] = wr[lane + 32*j];
    float bb = b_ih[gid];

    for (int v = 0; v < Vv; ++v) {
        const float4* ev = (const float4*)(sE + v*Ee);
        float a = 0.f;
        #pragma unroll
        for (int j = 0; j < 4; ++j) {
            float4 e = ev[lane + 32*j];
            a = fmaf(wreg[j].x, e.x, a); a = fmaf(wreg[j].y, e.y, a);
            a = fmaf(wreg[j].z, e.z, a); a = fmaf(wreg[j].w, e.w, a);
        }
        #pragma unroll
        for (int o = 16; o > 0; o >>= 1) a += __shfl_down_sync(0xffffffffu, a, o);
        if (lane == 0) g_GIT[(size_t)v*(3*Hh) + gid] = a + bb;
    }
}

// -------- WV[t][k] = dot(values[t], w_out[k][0:512]) ------------------------
__global__ void wv_kernel(const float* __restrict__ enc,
                          const float* __restrict__ w_out)
{
    extern __shared__ float sW[];
    for (int i = threadIdx.x; i < Vv*DVv; i += blockDim.x) {
        int k = i / DVv, j = i % DVv;
        sW[i] = w_out[(size_t)k*(DVv+Hh) + j];
    }
    __syncthreads();

    int lane  = threadIdx.x & 31;
    int gw    = blockIdx.x * (blockDim.x >> 5) + (threadIdx.x >> 5);
    int wspan = gridDim.x  * (blockDim.x >> 5);

    for (int t = gw; t < TENC; t += wspan) {
        float4 vreg[4];
        const float4* vr = (const float4*)(enc + (size_t)t*(DKk+DVv) + DKk);
        #pragma unroll
        for (int j = 0; j < 4; ++j) vreg[j] = vr[lane + 32*j];
        for (int k = 0; k < Vv; ++k) {
            const float4* wk = (const float4*)(sW + k*DVv);
            float a = 0.f;
            #pragma unroll
            for (int j = 0; j < 4; ++j) {
                float4 w = wk[lane + 32*j];
                a = fmaf(vreg[j].x, w.x, a); a = fmaf(vreg[j].y, w.y, a);
                a = fmaf(vreg[j].z, w.z, a); a = fmaf(vreg[j].w, w.w, a);
            }
            #pragma unroll
            for (int o = 16; o > 0; o >>= 1) a += __shfl_down_sync(0xffffffffu, a, o);
            if (lane == 0) g_WV[(size_t)t*Vv + k] = a;
        }
    }
}

// -------- persistent decoder ------------------------------------------------
__global__ void __launch_bounds__(TPB, 1)
dec_main(const float* __restrict__ enc,
         const float* __restrict__ hidden,
         const float* __restrict__ w_hh,
         const float* __restrict__ b_hh,
         const float* __restrict__ w_out,
         const float* __restrict__ b_out,
         float*       __restrict__ dout)
{
    __shared__ float  h_sh[Hh];
    __shared__ float  sGH[ROWS_PB][3];
    __shared__ float  sU[32][41];
    __shared__ float  sDen[32];
    __shared__ float  sRR[Vv+1][16];
    __shared__ float  sOH[Vv];
    __shared__ float  sGHall[3*Hh];
    __shared__ float  h_stage[Hh];
    __shared__ float4 s_vd;
    __shared__ int    s_bi;
    __shared__ float  s_inv;

    const int tid  = threadIdx.x;
    const int wid  = tid >> 5;
    const int lane = tid & 31;
    const int b    = blockIdx.x;

    float* attn = dout + (MAXLEN*Vv + 1);
    const int t0   = b * KEYS_PB;
    const int row0 = b * ROWS_PB;
    int   mylen = MAXLEN;                      // block0 warp0 lane0
    float e0 = 0.f, e1 = 0.f;

    // ---- preload h(-1) = hidden; gh = w_hh @ hidden; distributed h(0) ----
    if (tid < Hh/4) ((float4*)h_sh)[tid] = ((const float4*)hidden)[tid];
    __syncthreads();

    #define COMPUTE_GH()                                                          \
    do {                                                                           \
        if (wid < 12) {                                                            \
            int rl = wid / 3, gate = wid % 3;                                      \
            const float4* wr = (const float4*)(w_hh +                              \
                               (size_t)(gate*Hh + row0 + rl) * Hh);                \
            const float4* hv4g = (const float4*)h_sh;                              \
            float a = 0.f;                                                         \
            _Pragma("unroll")                                                      \
            for (int j = 0; j < 4; ++j) {                                          \
                float4 w = wr[lane + 32*j], h = hv4g[lane + 32*j];                 \
                a = fmaf(w.x, h.x, a); a = fmaf(w.y, h.y, a);                      \
                a = fmaf(w.z, h.z, a); a = fmaf(w.w, h.w, a);                      \
            }                                                                      \
            _Pragma("unroll")                                                      \
            for (int o = 16; o > 0; o >>= 1) a += __shfl_xor_sync(0xffffffffu, a, o); \
            if (lane == 0) sGH[rl][gate] = a;                                      \
        }                                                                          \
    } while (0)

    COMPUTE_GH();
    __syncthreads();

    // distributed combine for h(0) = GRU(hidden, embed[EOS]); publish tag 1
    if (wid == 0) {
        float hnv = 0.f;
        if (lane < ROWS_PB) {
            int row = row0 + lane;
            const float* git = g_GIT + (size_t)EOSI * (3*Hh);
            float ghr = sGH[lane][0] + b_hh[row];
            float ghz = sGH[lane][1] + b_hh[Hh + row];
            float ghn = sGH[lane][2] + b_hh[2*Hh + row];
            float gir = git[row], giz = git[Hh + row], gin = git[2*Hh + row];
            float rr = 1.f/(1.f + __expf(-(gir + ghr)));
            float zz = 1.f/(1.f + __expf(-(giz + ghz)));
            float x  = gin + rr*ghn;
            float ex = __expf(2.f*x);
            float nn = (ex - 1.f)/(ex + 1.f);
            hnv = (1.f - zz)*nn + zz*h_sh[row];
        }
        float up = __shfl_down_sync(0xffffffffu, hnv, 1);
        if (lane == 0) {
            float4 pk = make_float4(hnv, 1.f, up, 1.f);
            #pragma unroll
            for (int c = 0; c < NCPY; ++c) stcg4(&g_hT4R[c][2*b], pk);
        }
        if (lane == 2) {
            float4 pk = make_float4(hnv, 1.f, up, 1.f);
            #pragma unroll
            for (int c = 0; c < NCPY; ++c) stcg4(&g_hT4R[c][2*b + 1], pk);
        }
    }

    for (int s = 0; s < MAXLEN; ++s) {
        const float tagf = (float)(s + 1);
        const float vtag = (float)s;           // verdict(s-1) tag

        // ---- poll h(s) (tag s+1) and verdict(s-1) (tag s) ----
        {
            float4 hv;
            for (;;) {
                int ok = 1;
                if (tid < Hh/2) {
                    hv = ldcg4(&g_hT4R[b & (NCPY-1)][tid]);
                    ok = (hv.y >= tagf) && (hv.w >= tagf);
                } else if (tid == Hh/2 && s > 0) {
                    float4 v = ldcg4(&g_verdR[(b & (NCPY-1))*8]);
                    s_vd = v; ok = (v.z >= vtag);
                }
                if (__syncthreads_and(ok)) break;
            }
            if (tid < Hh/2) { h_sh[2*tid] = hv.x; h_sh[2*tid + 1] = hv.z; }
            __syncthreads();
        }

        // ---- store normalized attention row (s-1) from registers ----
        if (s > 0 && lane == 0) {
            float inv = s_vd.y;
            attn[(size_t)(s-1)*TENC + t0 + wid     ] = e0 * inv;
            attn[(size_t)(s-1)*TENC + t0 + wid + 32] = e1 * inv;
        }

        // ---- gh dots (warps 0..11): publish early, off critical path ----
        if (wid < 12) {
            int rl = wid / 3, gate = wid % 3;
            const float4* wr = (const float4*)(w_hh + (size_t)(gate*Hh + row0 + rl) * Hh);
            const float4* hv4g = (const float4*)h_sh;
            float a = 0.f;
            #pragma unroll
            for (int j = 0; j < 4; ++j) {
                float4 w = wr[lane + 32*j], h = hv4g[lane + 32*j];
                a = fmaf(w.x, h.x, a); a = fmaf(w.y, h.y, a);
                a = fmaf(w.z, h.z, a); a = fmaf(w.w, h.w, a);
            }
            #pragma unroll
            for (int o = 16; o > 0; o >>= 1) a += __shfl_xor_sync(0xffffffffu, a, o);
            if (lane == 0) stcg2(&g_ghT[(row0 + rl)*3 + gate], make_float2(a, tagf));
        }

        // ---- pOutH row (blocks 1..40, warp 31) ----
        if (b >= 1 && b <= Vv && wid == 31) {
            int k = b - 1;
            const float4* wr  = (const float4*)(w_out + (size_t)k*(DVv+Hh) + DVv);
            const float4* hv4 = (const float4*)h_sh;
            float acc = 0.f;
            #pragma unroll
            for (int j = 0; j < 4; ++j) {
                float4 w = wr[lane + 32*j], h = hv4[lane + 32*j];
                acc = fmaf(w.x, h.x, acc); acc = fmaf(w.y, h.y, acc);
                acc = fmaf(w.z, h.z, acc); acc = fmaf(w.w, h.w, acc);
            }
            #pragma unroll
            for (int o = 16; o > 0; o >>= 1) acc += __shfl_xor_sync(0xffffffffu, acc, o);
            if (lane == 0) stcg2(&g_pOHT[k], make_float2(acc, tagf));
        }

        // ---- attention over this block's 64 keys (L1-resident) ----
        {
            const float4* hv4 = (const float4*)h_sh;
            float4 h0 = hv4[lane], h1 = hv4[lane+32], h2 = hv4[lane+64], h3 = hv4[lane+96];
            float acc0 = 0.f, acc1 = 0.f, den = 0.f;
            #pragma unroll
            for (int it = 0; it < 2; ++it) {
                int t = t0 + wid + it*32;
                const float4* kr = (const float4*)(enc + (size_t)t*(DKk+DVv));
                float4 k0 = kr[lane], k1 = kr[lane+32], k2 = kr[lane+64], k3 = kr[lane+96];
                float a = 0.f;
                a = fmaf(k0.x, h0.x, a); a = fmaf(k0.y, h0.y, a);
                a = fmaf(k0.z, h0.z, a); a = fmaf(k0.w, h0.w, a);
                a = fmaf(k1.x, h1.x, a); a = fmaf(k1.y, h1.y, a);
                a = fmaf(k1.z, h1.z, a); a = fmaf(k1.w, h1.w, a);
                a = fmaf(k2.x, h2.x, a); a = fmaf(k2.y, h2.y, a);
                a = fmaf(k2.z, h2.z, a); a = fmaf(k2.w, h2.w, a);
                a = fmaf(k3.x, h3.x, a); a = fmaf(k3.y, h3.y, a);
                a = fmaf(k3.z, h3.z, a); a = fmaf(k3.w, h3.w, a);
                #pragma unroll
                for (int o = 16; o > 0; o >>= 1) a += __shfl_xor_sync(0xffffffffu, a, o);
                float e = __expf(a * SCALE);
                if (it == 0) e0 = e; else e1 = e;
                den += e;
                acc0 = fmaf(e, g_WV[(size_t)t*Vv + lane], acc0);
                if (lane < Vv - 32)
                    acc1 = fmaf(e, g_WV[(size_t)t*Vv + 32 + lane], acc1);
            }
            sU[wid][lane] = acc0;
            if (lane < Vv - 32) sU[wid][32 + lane] = acc1;
            if (lane == 0) sDen[wid] = den;
        }
        __syncthreads();

        // ---- publish tagged partials ----
        if (tid < Vv) {
            float a = 0.f;
            #pragma unroll
            for (int w = 0; w < 32; ++w) a += sU[w][tid];
            stcg2(&g_pUT[tid*NB + b], make_float2(a, tagf));
        } else if (tid == Vv) {
            float d = 0.f;
            #pragma unroll
            for (int w = 0; w < 32; ++w) d += sDen[w];
            stcg2(&g_pUT[Vv*NB + b], make_float2(d, tagf));
        }

        // ---- block 0: gather all, logits, argmax, full combine, publish ----
        if (b == 0) {
            const int r = tid >> 4, j = tid & 15;
            float acc = 0.f, pv = 0.f, ghA = 0.f, ghB = 0.f;
            for (;;) {
                int ok = 1;
                if (tid < 3*Hh/2) {           // 768 gh pairs
                    float4 e = ldcg4(((const float4*)g_ghT) + tid);
                    ok &= (e.y >= tagf) & (e.w >= tagf);
                    ghA = e.x; ghB = e.z;
                }
                if (tid < 656) {              // partial pairs
                    const float4* base = (const float4*)g_pUT + r*(NB/2);
                    acc = 0.f;
                    #pragma unroll
                    for (int q = 0; q < 4; ++q) {
                        float4 e = ldcg4(base + j + 16*q);
                        ok &= (e.y >= tagf) & (e.w >= tagf);
                        acc += e.x + e.z;
                    }
                }
                if (tid >= 784 && tid < 784 + Vv) {
                    float2 e = ldcg2(&g_pOHT[tid - 784]);
                    ok &= (e.y >= tagf);
                    pv = e.x;
                }
                if (__syncthreads_and(ok)) break;
            }
            if (tid < 3*Hh/2) { sGHall[2*tid] = ghA; sGHall[2*tid + 1] = ghB; }
            if (tid < 656) sRR[r][j] = acc;
            if (tid >= 784 && tid < 784 + Vv) sOH[tid - 784] = pv;
            __syncthreads();

            if (wid == 0) {
                float d = 0.f;
                #pragma unroll
                for (int q = 0; q < 16; ++q) d += sRR[Vv][q];
                float inv = 1.0f / d;

                float v1, v2 = -3.4e38f;
                int   k1 = lane, k2 = lane + 32;
                {
                    float a = 0.f;
                    #pragma unroll
                    for (int q = 0; q < 16; ++q) a += sRR[k1][q];
                    v1 = a*inv + sOH[k1] + b_out[k1];
                    dout[s*Vv + k1] = v1;
                }
                if (lane < Vv - 32) {
                    float a = 0.f;
                    #pragma unroll
                    for (int q = 0; q < 16; ++q) a += sRR[k2][q];
                    v2 = a*inv + sOH[k2] + b_out[k2];
                    dout[s*Vv + k2] = v2;
                }
                float bv; int bi;
                if (v2 > v1) { bv = v2; bi = k2; } else { bv = v1; bi = k1; }
                #pragma unroll
                for (int o = 16; o > 0; o >>= 1) {
                    float ov = __shfl_xor_sync(0xffffffffu, bv, o);
                    int   oi = __shfl_xor_sync(0xffffffffu, bi, o);
                    if (ov > bv || (ov == bv && oi < bi)) { bv = ov; bi = oi; }
                }
                if (lane == 0) {
                    s_bi = bi; s_inv = inv;
                    if (bi == EOSI && mylen == MAXLEN) mylen = s;
                    if (s == MAXLEN-1) dout[MAXLEN*Vv] = (float)mylen;   // lens
                }
            }
            __syncthreads();

            // full 512-row combine -> h(s+1)
            if (tid < Hh) {
                int row = tid;
                const float* git = g_GIT + (size_t)s_bi * (3*Hh);
                float g0 = sGHall[3*row], g1 = sGHall[3*row+1], g2 = sGHall[3*row+2];
                float ghr = g0 + b_hh[row];
                float ghz = g1 + b_hh[Hh + row];
                float ghn = g2 + b_hh[2*Hh + row];
                float gir = git[row], giz = git[Hh + row], gin = git[2*Hh + row];
                float rr = 1.f/(1.f + __expf(-(gir + ghr)));
                float zz = 1.f/(1.f + __expf(-(giz + ghz)));
                float x  = gin + rr*ghn;
                float ex = __expf(2.f*x);
                float nn = (ex - 1.f)/(ex + 1.f);
                h_stage[row] = (1.f - zz)*nn + zz*h_sh[row];
            }
            __syncthreads();

            // publish h(s+1) tag s+2 to all copies + verdict(s) tag s+1
            if (tid < Hh/2) {
                float4 pk = make_float4(h_stage[2*tid], tagf + 1.f,
                                        h_stage[2*tid + 1], tagf + 1.f);
                #pragma unroll
                for (int c = 0; c < NCPY; ++c) stcg4(&g_hT4R[c][tid], pk);
            }
            if (wid == 16 && lane < NCPY)
                stcg4(&g_verdR[lane*8], make_float4((float)s_bi, s_inv, tagf, 0.f));
        }
    }

    // ---- tail: consume verdict(199) for final attention row ----
    {
        const float ptag = (float)MAXLEN;
        for (;;) {
            int ok = 1;
            if (tid == 0) {
                float4 v = ldcg4(&g_verdR[(b & (NCPY-1))*8]);
                s_vd = v; ok = (v.z >= ptag);
            }
            if (__syncthreads_and(ok)) break;
        }
        if (lane == 0) {
            float inv = s_vd.y;
            attn[(size_t)(MAXLEN-1)*TENC + t0 + wid     ] = e0 * inv;
            attn[(size_t)(MAXLEN-1)*TENC + t0 + wid + 32] = e1 * inv;
        }
    }
}

// ---------------------------------------------------------------------------
extern "C" void kernel_launch(void* const* d_in, const int* in_sizes, int n_in,
                              void* d_out, int out_size)
{
    const float* enc    = (const float*)d_in[0];
    const float* hidden = (const float*)d_in[1];
    const float* embed  = (const float*)d_in[2];
    const float* w_ih   = (const float*)d_in[3];
    const float* w_hh   = (const float*)d_in[4];
    const float* b_ih   = (const float*)d_in[5];
    const float* b_hh   = (const float*)d_in[6];
    const float* w_out  = (const float*)d_in[7];
    const float* b_out  = (const float*)d_in[8];
    float*       out    = (float*)d_out;

    cudaFuncSetAttribute(gi_kernel, cudaFuncAttributeMaxDynamicSharedMemorySize, 81920);
    cudaFuncSetAttribute(wv_kernel, cudaFuncAttributeMaxDynamicSharedMemorySize, 81920);

    reset_kernel<<<1, 1024>>>();
    gi_kernel<<<192, 256, 81920>>>(w_ih, b_ih, embed);
    wv_kernel<<<256, 256, 81920>>>(enc, w_out);
    dec_main<<<NB, TPB>>>(enc, hidden, w_hh, b_hh, w_out, b_out, out);
}